// round 2
// baseline (speedup 1.0000x reference)
#include <cuda_runtime.h>
#include <math.h>

// Problem constants
#define BATCH  2048
#define HID    512
#define INDIM  128
#define OUTDIM 128
#define SEQ    128

// Tiling
#define BM 64
#define BN 64
#define BK 16
#define PAD 68          // 64 + 4 pad, keeps 16B alignment for vector smem access
#define NTHREADS 256

typedef unsigned long long u64;

// Ping-pong hidden state (2 x 4 MB). Static device scratch (no allocations allowed).
__device__ float g_h[2 * BATCH * HID];

// ---------------- packed f32x2 helpers (Blackwell FFMA2) ----------------

__device__ __forceinline__ u64 pack2(float lo, float hi) {
    u64 r;
    asm("mov.b64 %0, {%1, %2};" : "=l"(r) : "f"(lo), "f"(hi));
    return r;
}

__device__ __forceinline__ float2 unpack2(u64 v) {
    float2 f;
    asm("mov.b64 {%0, %1}, %2;" : "=f"(f.x), "=f"(f.y) : "l"(v));
    return f;
}

__device__ __forceinline__ u64 fma2(u64 a, u64 b, u64 c) {
    u64 d;
    asm("fma.rn.f32x2 %0, %1, %2, %3;" : "=l"(d) : "l"(a), "l"(b), "l"(c));
    return d;
}

__device__ __forceinline__ float gru_comb(float pr, float pz, float pin, float phn, float ho) {
    float r  = 1.0f / (1.0f + expf(-pr));
    float z  = 1.0f / (1.0f + expf(-pz));
    float nn = tanhf(pin + r * phn);
    return (1.0f - z) * nn + z * ho;
}

// Inner-product microkernel over one BK slice.
// ACCN = accin (x phase) or acchn (h phase): the n-gate keeps separate
// accumulators because n = tanh(i_n + r * h_n).
#define TILE_COMPUTE(ACCN)                                                        \
    _Pragma("unroll")                                                             \
    for (int kk = 0; kk < BK; ++kk) {                                             \
        const float4 av = *reinterpret_cast<const float4*>(&As[kk][ty << 2]);     \
        u64 a2[4];                                                                \
        a2[0] = pack2(av.x, av.x);                                                \
        a2[1] = pack2(av.y, av.y);                                                \
        a2[2] = pack2(av.z, av.z);                                                \
        a2[3] = pack2(av.w, av.w);                                                \
        const ulonglong2 vr = *reinterpret_cast<const ulonglong2*>(&Br[kk][tx << 2]); \
        const ulonglong2 vz = *reinterpret_cast<const ulonglong2*>(&Bz[kk][tx << 2]); \
        const ulonglong2 vn = *reinterpret_cast<const ulonglong2*>(&Bn[kk][tx << 2]); \
        _Pragma("unroll")                                                         \
        for (int i = 0; i < 4; ++i) {                                             \
            accr[i][0] = fma2(a2[i], vr.x, accr[i][0]);                           \
            accr[i][1] = fma2(a2[i], vr.y, accr[i][1]);                           \
            accz[i][0] = fma2(a2[i], vz.x, accz[i][0]);                           \
            accz[i][1] = fma2(a2[i], vz.y, accz[i][1]);                           \
            ACCN[i][0] = fma2(a2[i], vn.x, ACCN[i][0]);                           \
            ACCN[i][1] = fma2(a2[i], vn.y, ACCN[i][1]);                           \
        }                                                                         \
    }

// ---------------- fused GRU step: h_next = GRUCell(x, h_prev) ----------------
// h_prev = hext (step 0) or g_h slot (wsel^1); h_next = g_h slot wsel.
// Per output element (b, n):
//   r  = sigmoid(x.Wr_ih + h.Wr_hh + br_ih + br_hh)
//   z  = sigmoid(x.Wz_ih + h.Wz_hh + bz_ih + bz_hh)
//   nn = tanh(x.Wn_ih + bn_ih + r*(h.Wn_hh + bn_hh))
//   h' = (1-z)*nn + z*h
__global__ __launch_bounds__(NTHREADS)
void gru_step_kernel(const float* __restrict__ x, long x_stride,   // x == nullptr on step 0
                     const float* __restrict__ hext,               // external h0 (step 0 only)
                     int wsel,                                     // g_h slot to write
                     const float* __restrict__ w_ih,   // (3H, INDIM)
                     const float* __restrict__ w_hh,   // (3H, HID)
                     const float* __restrict__ b_ih,   // (3H)
                     const float* __restrict__ b_hh)   // (3H)
{
    const float* h_prev = hext ? hext : (g_h + (long)(wsel ^ 1) * BATCH * HID);
    float*       h_next = g_h + (long)wsel * BATCH * HID;

    __shared__ __align__(16) float As[BK][PAD];
    __shared__ __align__(16) float Br[BK][PAD];
    __shared__ __align__(16) float Bz[BK][PAD];
    __shared__ __align__(16) float Bn[BK][PAD];

    const int m0 = blockIdx.x * BM;
    const int n0 = blockIdx.y * BN;
    const int t  = threadIdx.x;
    const int tx = t & 15;          // 0..15 -> 4 output cols each
    const int ty = t >> 4;          // 0..15 -> 4 output rows each
    const int lrow = t >> 2;        // 0..63  (load row)
    const int lc4  = (t & 3) << 2;  // 0,4,8,12 (load col group)

    u64 accr[4][2], accz[4][2], accin[4][2], acchn[4][2];
#pragma unroll
    for (int i = 0; i < 4; ++i)
#pragma unroll
        for (int j = 0; j < 2; ++j)
            accr[i][j] = accz[i][j] = accin[i][j] = acchn[i][j] = 0ull;

    // ---- phase 0: x @ w_ih^T  (skipped on step 0, x == 0) ----
    if (x != nullptr) {
        for (int kb = 0; kb < INDIM; kb += BK) {
            {
                const float4 v = *reinterpret_cast<const float4*>(
                    &x[(long)(m0 + lrow) * x_stride + kb + lc4]);
                As[lc4 + 0][lrow] = v.x; As[lc4 + 1][lrow] = v.y;
                As[lc4 + 2][lrow] = v.z; As[lc4 + 3][lrow] = v.w;
            }
            {
                const int wrow = n0 + lrow;
                const float4 vr = *reinterpret_cast<const float4*>(
                    &w_ih[(long)wrow * INDIM + kb + lc4]);
                Br[lc4 + 0][lrow] = vr.x; Br[lc4 + 1][lrow] = vr.y;
                Br[lc4 + 2][lrow] = vr.z; Br[lc4 + 3][lrow] = vr.w;
                const float4 vz = *reinterpret_cast<const float4*>(
                    &w_ih[(long)(HID + wrow) * INDIM + kb + lc4]);
                Bz[lc4 + 0][lrow] = vz.x; Bz[lc4 + 1][lrow] = vz.y;
                Bz[lc4 + 2][lrow] = vz.z; Bz[lc4 + 3][lrow] = vz.w;
                const float4 vn = *reinterpret_cast<const float4*>(
                    &w_ih[(long)(2 * HID + wrow) * INDIM + kb + lc4]);
                Bn[lc4 + 0][lrow] = vn.x; Bn[lc4 + 1][lrow] = vn.y;
                Bn[lc4 + 2][lrow] = vn.z; Bn[lc4 + 3][lrow] = vn.w;
            }
            __syncthreads();
            TILE_COMPUTE(accin)
            __syncthreads();
        }
    }

    // ---- phase 1: h @ w_hh^T ----
    for (int kb = 0; kb < HID; kb += BK) {
        {
            const float4 v = *reinterpret_cast<const float4*>(
                &h_prev[(long)(m0 + lrow) * HID + kb + lc4]);
            As[lc4 + 0][lrow] = v.x; As[lc4 + 1][lrow] = v.y;
            As[lc4 + 2][lrow] = v.z; As[lc4 + 3][lrow] = v.w;
        }
        {
            const int wrow = n0 + lrow;
            const float4 vr = *reinterpret_cast<const float4*>(
                &w_hh[(long)wrow * HID + kb + lc4]);
            Br[lc4 + 0][lrow] = vr.x; Br[lc4 + 1][lrow] = vr.y;
            Br[lc4 + 2][lrow] = vr.z; Br[lc4 + 3][lrow] = vr.w;
            const float4 vz = *reinterpret_cast<const float4*>(
                &w_hh[(long)(HID + wrow) * HID + kb + lc4]);
            Bz[lc4 + 0][lrow] = vz.x; Bz[lc4 + 1][lrow] = vz.y;
            Bz[lc4 + 2][lrow] = vz.z; Bz[lc4 + 3][lrow] = vz.w;
            const float4 vn = *reinterpret_cast<const float4*>(
                &w_hh[(long)(2 * HID + wrow) * HID + kb + lc4]);
            Bn[lc4 + 0][lrow] = vn.x; Bn[lc4 + 1][lrow] = vn.y;
            Bn[lc4 + 2][lrow] = vn.z; Bn[lc4 + 3][lrow] = vn.w;
        }
        __syncthreads();
        TILE_COMPUTE(acchn)
        __syncthreads();
    }

    // ---- epilogue: gates + state update ----
    const int ncol = n0 + (tx << 2);
    const float4 bir = *reinterpret_cast<const float4*>(&b_ih[ncol]);
    const float4 biz = *reinterpret_cast<const float4*>(&b_ih[HID + ncol]);
    const float4 bin = *reinterpret_cast<const float4*>(&b_ih[2 * HID + ncol]);
    const float4 bhr = *reinterpret_cast<const float4*>(&b_hh[ncol]);
    const float4 bhz = *reinterpret_cast<const float4*>(&b_hh[HID + ncol]);
    const float4 bhn = *reinterpret_cast<const float4*>(&b_hh[2 * HID + ncol]);

#pragma unroll
    for (int i = 0; i < 4; ++i) {
        const long row = m0 + (ty << 2) + i;
        const float4 ho = *reinterpret_cast<const float4*>(&h_prev[row * HID + ncol]);
        const float2 r0 = unpack2(accr[i][0]),  r1 = unpack2(accr[i][1]);
        const float2 z0 = unpack2(accz[i][0]),  z1 = unpack2(accz[i][1]);
        const float2 i0 = unpack2(accin[i][0]), i1 = unpack2(accin[i][1]);
        const float2 g0 = unpack2(acchn[i][0]), g1 = unpack2(acchn[i][1]);
        float4 o;
        o.x = gru_comb(r0.x + bir.x + bhr.x, z0.x + biz.x + bhz.x,
                       i0.x + bin.x, g0.x + bhn.x, ho.x);
        o.y = gru_comb(r0.y + bir.y + bhr.y, z0.y + biz.y + bhz.y,
                       i0.y + bin.y, g0.y + bhn.y, ho.y);
        o.z = gru_comb(r1.x + bir.z + bhr.z, z1.x + biz.z + bhz.z,
                       i1.x + bin.z, g1.x + bhn.z, ho.z);
        o.w = gru_comb(r1.y + bir.w + bhr.w, z1.y + biz.w + bhz.w,
                       i1.y + bin.w, g1.y + bhn.w, ho.w);
        *reinterpret_cast<float4*>(&h_next[row * HID + ncol]) = o;
    }
}

// ---------------- FC readout: y = h @ fc_w^T + fc_b, written into d_out ----------------
__global__ __launch_bounds__(NTHREADS)
void fc_kernel(int hsel,                         // g_h slot holding current h
               const float* __restrict__ fc_w,   // (OUTDIM, HID)
               const float* __restrict__ fc_b,   // (OUTDIM)
               float* __restrict__ y, long y_stride)  // y[b*y_stride + o]
{
    const float* h = g_h + (long)hsel * BATCH * HID;

    __shared__ __align__(16) float As[BK][PAD];
    __shared__ __align__(16) float Bs[BK][PAD];

    const int m0 = blockIdx.x * BM;
    const int n0 = blockIdx.y * BN;
    const int t  = threadIdx.x;
    const int tx = t & 15;
    const int ty = t >> 4;
    const int lrow = t >> 2;
    const int lc4  = (t & 3) << 2;

    u64 acc[4][2];
#pragma unroll
    for (int i = 0; i < 4; ++i) { acc[i][0] = 0ull; acc[i][1] = 0ull; }

    for (int kb = 0; kb < HID; kb += BK) {
        {
            const float4 v = *reinterpret_cast<const float4*>(
                &h[(long)(m0 + lrow) * HID + kb + lc4]);
            As[lc4 + 0][lrow] = v.x; As[lc4 + 1][lrow] = v.y;
            As[lc4 + 2][lrow] = v.z; As[lc4 + 3][lrow] = v.w;
        }
        {
            const float4 v = *reinterpret_cast<const float4*>(
                &fc_w[(long)(n0 + lrow) * HID + kb + lc4]);
            Bs[lc4 + 0][lrow] = v.x; Bs[lc4 + 1][lrow] = v.y;
            Bs[lc4 + 2][lrow] = v.z; Bs[lc4 + 3][lrow] = v.w;
        }
        __syncthreads();
#pragma unroll
        for (int kk = 0; kk < BK; ++kk) {
            const float4 av = *reinterpret_cast<const float4*>(&As[kk][ty << 2]);
            u64 a2[4];
            a2[0] = pack2(av.x, av.x);
            a2[1] = pack2(av.y, av.y);
            a2[2] = pack2(av.z, av.z);
            a2[3] = pack2(av.w, av.w);
            const ulonglong2 vb = *reinterpret_cast<const ulonglong2*>(&Bs[kk][tx << 2]);
#pragma unroll
            for (int i = 0; i < 4; ++i) {
                acc[i][0] = fma2(a2[i], vb.x, acc[i][0]);
                acc[i][1] = fma2(a2[i], vb.y, acc[i][1]);
            }
        }
        __syncthreads();
    }

    const int ncol = n0 + (tx << 2);
    const float4 bb = *reinterpret_cast<const float4*>(&fc_b[ncol]);
#pragma unroll
    for (int i = 0; i < 4; ++i) {
        const long row = m0 + (ty << 2) + i;
        const float2 p0 = unpack2(acc[i][0]);
        const float2 p1 = unpack2(acc[i][1]);
        float4 o;
        o.x = p0.x + bb.x;
        o.y = p0.y + bb.y;
        o.z = p1.x + bb.z;
        o.w = p1.y + bb.w;
        *reinterpret_cast<float4*>(&y[row * y_stride + ncol]) = o;
    }
}

// ---------------- launch ----------------
// inputs (metadata order): hidden, w_ih, w_hh, b_ih, b_hh, fc_w, fc_b, seq_len
extern "C" void kernel_launch(void* const* d_in, const int* in_sizes, int n_in,
                              void* d_out, int out_size)
{
    const float* hidden = (const float*)d_in[0];
    const float* w_ih   = (const float*)d_in[1];
    const float* w_hh   = (const float*)d_in[2];
    const float* b_ih   = (const float*)d_in[3];
    const float* b_hh   = (const float*)d_in[4];
    const float* fc_w   = (const float*)d_in[5];
    const float* fc_b   = (const float*)d_in[6];
    float* out = (float*)d_out;

    const dim3 gridG(BATCH / BM, HID / BN);     // 32 x 8
    const dim3 gridF(BATCH / BM, OUTDIM / BN);  // 32 x 2
    const long xs = (long)SEQ * OUTDIM;         // batch-row stride inside d_out

    for (int s = 0; s < SEQ; ++s) {
        // x for step s is y_{s-1}, which lives at seq index SEQ-s in d_out
        const float* x    = (s == 0) ? nullptr : out + (long)(SEQ - s) * OUTDIM;
        const float* hext = (s == 0) ? hidden  : nullptr;
        const int    wsel = s & 1;               // g_h slot written by step s
        gru_step_kernel<<<gridG, NTHREADS>>>(x, xs, hext, wsel, w_ih, w_hh, b_ih, b_hh);
        // y_s goes to seq index SEQ-1-s (reference reverses the seq dim)
        fc_kernel<<<gridF, NTHREADS>>>(wsel, fc_w, fc_b,
                                       out + (long)(SEQ - 1 - s) * OUTDIM, xs);
    }
}